// round 5
// baseline (speedup 1.0000x reference)
#include <cuda_runtime.h>
#include <stdint.h>

// out[n,o] = -|eta| * sum_i |x[n,i] - w[o,i]|
// N=2048, K=1024, O=2048, fp32.
//
// Round 5: L0 I-cache fit. The k-body is unrolled only 2x so the hot loop
// is ~4.4KB (< 6KB L0), instead of the 9-17KB straight-line blocks of
// earlier rounds that streamed from L1.5 every iteration and capped issue
// at ~68%. Core math unchanged: packed f32x2 adds (fma pipe) + LOP3
// sign-clear abs (alu pipe), 16 outputs/thread, 3 CTAs/SM, cp.async
// double-buffered 64x64 tiles, pre-negated w.

#define N_ROWS 2048
#define K_DIM  1024
#define O_COLS 2048

#define TN 64
#define TO 64
#define KT 32
#define SS 36                        // row stride (floats); conflict-free
#define NTILES (K_DIM / KT)          // 32
#define BUF_FLOATS ((TN + TO) * SS)  // 4608 floats = 18432 B per buffer

__device__ float g_negw[O_COLS * K_DIM];   // 8 MB scratch: -w

__global__ void negw_kernel(const float* __restrict__ w)
{
    int i = blockIdx.x * blockDim.x + threadIdx.x;   // float4 index
    float4 v = ((const float4*)w)[i];
    float4 r;
    r.x = -v.x; r.y = -v.y; r.z = -v.z; r.w = -v.w;
    ((float4*)g_negw)[i] = r;
}

__device__ __forceinline__ void cp16(float* dst, const float* src)
{
    unsigned s = (unsigned)__cvta_generic_to_shared(dst);
    asm volatile("cp.async.cg.shared.global [%0], [%1], 16;"
                 :: "r"(s), "l"(src) : "memory");
}
__device__ __forceinline__ void cp_commit()
{
    asm volatile("cp.async.commit_group;" ::: "memory");
}
__device__ __forceinline__ void cp_wait_all()
{
    asm volatile("cp.async.wait_group 0;" ::: "memory");
}

// packed: d = x + (-w); d = |d| per half; acc += d
#define STEP(xr, wr, a) do {                                             \
    uint64_t d_;                                                         \
    asm("add.rn.f32x2 %0, %1, %2;" : "=l"(d_) : "l"(xr), "l"(wr));       \
    asm("{\n\t"                                                          \
        ".reg .b32 lo, hi;\n\t"                                          \
        "mov.b64 {lo, hi}, %0;\n\t"                                      \
        "and.b32 lo, lo, 0x7fffffff;\n\t"                                \
        "and.b32 hi, hi, 0x7fffffff;\n\t"                                \
        "mov.b64 %0, {lo, hi};\n\t"                                      \
        "}" : "+l"(d_));                                                 \
    asm("add.rn.f32x2 %0, %0, %1;" : "+l"(a) : "l"(d_));                 \
} while (0)

__global__ __launch_bounds__(256, 3)
void adder_linear_kernel(const float* __restrict__ x,
                         const float* __restrict__ eta,
                         float* __restrict__ out)
{
    __shared__ float smem[2 * BUF_FLOATS];   // 36864 B -> 3 CTAs/SM

    const int tid    = threadIdx.x;
    const int wid    = tid >> 5;
    const int lane   = tid & 31;
    const int warp_n = wid & 1;          // 0..1
    const int warp_o = wid >> 1;         // 0..3
    const int lane_n = lane & 7;         // 0..7
    const int lane_o = lane >> 3;        // 0..3

    const int n0 = blockIdx.y * TN;
    const int o0 = blockIdx.x * TO;

    // thread outputs: n = n0 + tn + i*8 (i<4), o = o0 + to + j*4 (j<4)
    const int tn = warp_n * 32 + lane_n;
    const int to = warp_o * 16 + lane_o;

    uint64_t acc[4][4];
    #pragma unroll
    for (int i = 0; i < 4; i++)
        #pragma unroll
        for (int j = 0; j < 4; j++)
            acc[i][j] = 0ull;

    auto prefetch = [&](float* buf, int kt) {
        float* sxp = buf;
        float* swp = buf + TN * SS;
        #pragma unroll
        for (int it = 0; it < 2; it++) {
            int idx = tid + 256 * it;          // 0..511
            int r = idx >> 3, q = idx & 7;
            cp16(&sxp[r * SS + q * 4],
                 &x[(size_t)(n0 + r) * K_DIM + kt + q * 4]);
        }
        #pragma unroll
        for (int it = 0; it < 2; it++) {
            int idx = tid + 256 * it;
            int r = idx >> 3, q = idx & 7;
            cp16(&swp[r * SS + q * 4],
                 &g_negw[(size_t)(o0 + r) * K_DIM + kt + q * 4]);
        }
    };

    prefetch(smem, 0);
    cp_commit();

    for (int t = 0; t < NTILES; t++) {
        cp_wait_all();          // tile t landed
        __syncthreads();        // other buffer free for refill

        if (t + 1 < NTILES) {
            prefetch((t & 1) ? smem : smem + BUF_FLOATS, (t + 1) * KT);
            cp_commit();
        }

        const float* sb = (t & 1) ? smem + BUF_FLOATS : smem;
        const float* xb = sb + tn * SS;
        const float* wb = sb + TN * SS + to * SS;

        // hot loop: 2x-unrolled 4-k body, ~4.4KB of SASS -> L0-resident
        #pragma unroll 2
        for (int kk = 0; kk < KT; kk += 4) {
            uint64_t wq[4][2], xq[4][2];
            #pragma unroll
            for (int j = 0; j < 4; j++) {
                ulonglong2 v = *(const ulonglong2*)(wb + j * 4 * SS + kk);
                wq[j][0] = v.x; wq[j][1] = v.y;
            }
            #pragma unroll
            for (int i = 0; i < 4; i++) {
                ulonglong2 v = *(const ulonglong2*)(xb + i * 8 * SS + kk);
                xq[i][0] = v.x; xq[i][1] = v.y;
            }
            #pragma unroll
            for (int i = 0; i < 4; i++) {
                #pragma unroll
                for (int j = 0; j < 4; j++) {
                    STEP(xq[i][0], wq[j][0], acc[i][j]);
                    STEP(xq[i][1], wq[j][1], acc[i][j]);
                }
            }
        }
    }

    const float scale = -fabsf(eta[0]);

    #pragma unroll
    for (int i = 0; i < 4; i++) {
        int n = n0 + tn + i * 8;
        #pragma unroll
        for (int j = 0; j < 4; j++) {
            int o = o0 + to + j * 4;
            float lo, hi;
            asm("mov.b64 {%0, %1}, %2;" : "=f"(lo), "=f"(hi) : "l"(acc[i][j]));
            out[(size_t)n * O_COLS + o] = (lo + hi) * scale;
        }
    }
}

extern "C" void kernel_launch(void* const* d_in, const int* in_sizes, int n_in,
                              void* d_out, int out_size)
{
    const float* x   = (const float*)d_in[0];   // [2048, 1024]
    const float* w   = (const float*)d_in[1];   // [2048, 1024]
    const float* eta = (const float*)d_in[2];   // [1]
    float* out = (float*)d_out;                 // [2048, 2048]

    // pre-pass: g_negw = -w
    negw_kernel<<<O_COLS * K_DIM / 4 / 256, 256>>>(w);

    dim3 grid(O_COLS / TO, N_ROWS / TN);        // (32, 32) = 1024 blocks
    adder_linear_kernel<<<grid, 256>>>(x, eta, out);
}